// round 6
// baseline (speedup 1.0000x reference)
#include <cuda_runtime.h>
#include <cuda_bf16.h>
#include <cstddef>

#define NPART 128
#define NDIM  128
#define BATCH 4096
#define TILE_B 48
#define NTHREADS 512

// ---------------------------------------------------------------------------
// Fully fused kernel: one CTA per particle, 512 threads.
//   - warp-shuffle softmax (warp 0 only)
//   - sigma LDGs issued first, randind scan overlapped under them
//   - TILE_B=48 single-tile GEMM (4i x 3b per thread), loop for rare overflow
// ---------------------------------------------------------------------------
__global__ __launch_bounds__(NTHREADS) void fused_k(
    const float* __restrict__ gaussian,
    const float* __restrict__ logp,
    const float* __restrict__ pos,
    const float* __restrict__ sigma,
    const int*   __restrict__ randind,
    float*       __restrict__ out,
    float*       __restrict__ wout,
    float*       __restrict__ rout)
{
    extern __shared__ float smem[];
    float* sig_t = smem;                 // [128][128] transposed sigma (64KB)
    float* ysh   = smem + NDIM * NDIM;   // [TILE_B][128] (24KB)
    __shared__ int   list[BATCH];        // this CTA's sample indices (16KB)
    __shared__ int   s_count;
    __shared__ float s_pp;

    const int p   = blockIdx.x;
    const int tid = threadIdx.x;

    if (tid == 0) s_count = 0;
    __syncthreads();                     // s_count visible before atomics

    // ---- issue sigma loads first (long latency, no dependencies) ----
    const int si = tid & 127;            // row i
    const int jh = (tid >> 7) * 32;      // 4 j-chunks of 32 floats
    float4 sv[8];
    {
        const float4* srow =
            (const float4*)(sigma + ((size_t)p * NDIM + si) * NDIM + jh);
        #pragma unroll
        for (int jj = 0; jj < 8; jj++) sv[jj] = __ldg(&srow[jj]);
    }

    // ---- softmax via warp 0 shuffles (overlapped with sigma LDGs) ----
    if (tid < 32) {
        float v0 = logp[tid],      v1 = logp[tid + 32];
        float v2 = logp[tid + 64], v3 = logp[tid + 96];
        float m = fmaxf(fmaxf(v0, v1), fmaxf(v2, v3));
        #pragma unroll
        for (int s = 16; s > 0; s >>= 1)
            m = fmaxf(m, __shfl_xor_sync(0xffffffffu, m, s));
        float e = __expf(v0 - m) + __expf(v1 - m) + __expf(v2 - m) + __expf(v3 - m);
        #pragma unroll
        for (int s = 16; s > 0; s >>= 1)
            e += __shfl_xor_sync(0xffffffffu, e, s);
        if (tid == 0) s_pp = __expf(logp[p] - m) / e;
    }

    // ---- scan randind, collect own samples (overlapped with sigma LDGs) ----
    int myb[BATCH / NTHREADS];
    int myr[BATCH / NTHREADS];
    #pragma unroll
    for (int k = 0; k < BATCH / NTHREADS; k++) {
        int b = tid + k * NTHREADS;
        myb[k] = b;
        myr[k] = __ldg(&randind[b]);
    }
    #pragma unroll
    for (int k = 0; k < BATCH / NTHREADS; k++) {
        if (myr[k] == p) {
            int slot = atomicAdd(&s_count, 1);
            list[slot] = myb[k];
        }
    }

    // ---- store sigma transposed ----
    #pragma unroll
    for (int jj = 0; jj < 8; jj++) {
        int j = jh + jj * 4;
        sig_t[(j + 0) * NDIM + si] = sv[jj].x;
        sig_t[(j + 1) * NDIM + si] = sv[jj].y;
        sig_t[(j + 2) * NDIM + si] = sv[jj].z;
        sig_t[(j + 3) * NDIM + si] = sv[jj].w;
    }

    __syncthreads();                     // list, count, sig_t, s_pp ready
    const int count = s_count;
    const float pp = s_pp;

    // ---- aux outputs for my collected samples ----
    #pragma unroll
    for (int k = 0; k < BATCH / NTHREADS; k++) {
        if (myr[k] == p) {
            int b = myb[k];
            if (wout) wout[b] = pp;
            if (rout) rout[b] = (float)p;
        }
    }

    // ---- batched matvec: thread = 4i x 3b ----
    const int tx = tid & 31;             // 32 i-groups of 4
    const int ty = tid >> 5;             // 16 b-groups of 3
    const int i0 = tx * 4;

    const float4 pv = __ldg((const float4*)(pos + (size_t)p * NDIM + i0));

    const int ntiles = (count + TILE_B - 1) / TILE_B;   // 1 for ~all CTAs

    for (int t = 0; t < ntiles; t++) {
        const int base = t * TILE_B;

        if (t > 0) __syncthreads();
        // stage y tile: TILE_B rows x 32 float4 = 1536 float4, 3 per thread
        #pragma unroll
        for (int idx = tid; idx < TILE_B * 32; idx += NTHREADS) {
            int bl = idx >> 5;
            int j4 = idx & 31;
            int gi = base + bl;
            float4 v = make_float4(0.f, 0.f, 0.f, 0.f);
            if (gi < count)
                v = __ldg((const float4*)(gaussian + (size_t)list[gi] * NDIM) + j4);
            *((float4*)(ysh + bl * NDIM) + j4) = v;
        }
        __syncthreads();

        float a0[4] = {0.f, 0.f, 0.f, 0.f};
        float a1[4] = {0.f, 0.f, 0.f, 0.f};
        float a2[4] = {0.f, 0.f, 0.f, 0.f};
        const float* y0 = ysh + (ty * 3 + 0) * NDIM;
        const float* y1 = ysh + (ty * 3 + 1) * NDIM;
        const float* y2 = ysh + (ty * 3 + 2) * NDIM;

        #pragma unroll 8
        for (int j = 0; j < NDIM; j++) {
            float4 s = *(const float4*)(sig_t + j * NDIM + i0);
            float ya = y0[j], yb = y1[j], yc = y2[j];
            a0[0] = fmaf(s.x, ya, a0[0]); a0[1] = fmaf(s.y, ya, a0[1]);
            a0[2] = fmaf(s.z, ya, a0[2]); a0[3] = fmaf(s.w, ya, a0[3]);
            a1[0] = fmaf(s.x, yb, a1[0]); a1[1] = fmaf(s.y, yb, a1[1]);
            a1[2] = fmaf(s.z, yb, a1[2]); a1[3] = fmaf(s.w, yb, a1[3]);
            a2[0] = fmaf(s.x, yc, a2[0]); a2[1] = fmaf(s.y, yc, a2[1]);
            a2[2] = fmaf(s.z, yc, a2[2]); a2[3] = fmaf(s.w, yc, a2[3]);
        }

        #pragma unroll
        for (int bb = 0; bb < 3; bb++) {
            int gi = base + ty * 3 + bb;
            if (gi < count) {
                int b = list[gi];
                const float* a = (bb == 0) ? a0 : (bb == 1) ? a1 : a2;
                float4 o;
                o.x = pv.x + a[0]; o.y = pv.y + a[1];
                o.z = pv.z + a[2]; o.w = pv.w + a[3];
                *(float4*)(out + (size_t)b * NDIM + i0) = o;
            }
        }
    }
}

// ---------------------------------------------------------------------------
// Launch
// ---------------------------------------------------------------------------
extern "C" void kernel_launch(void* const* d_in, const int* in_sizes, int n_in,
                              void* d_out, int out_size)
{
    const float* gaussian = nullptr;
    const float* logp     = nullptr;
    const float* pos      = nullptr;
    const float* sigma    = nullptr;
    const int*   randind  = nullptr;

    for (int k = 0; k < n_in; k++) {
        switch (in_sizes[k]) {
            case BATCH * NDIM:        gaussian = (const float*)d_in[k]; break;
            case NPART:               logp     = (const float*)d_in[k]; break;
            case NPART * NDIM:        pos      = (const float*)d_in[k]; break;
            case NPART * NDIM * NDIM: sigma    = (const float*)d_in[k]; break;
            case BATCH:               randind  = (const int*)d_in[k];   break;
            default: break;
        }
    }

    float* out  = (float*)d_out;
    float* wout = nullptr;
    float* rout = nullptr;
    const int OUT_MAIN = BATCH * NDIM;
    if (out_size >= OUT_MAIN + BATCH)     wout = out + OUT_MAIN;
    if (out_size >= OUT_MAIN + 2 * BATCH) rout = out + OUT_MAIN + BATCH;

    const int smem_bytes = (NDIM * NDIM + TILE_B * NDIM) * (int)sizeof(float); // 90112
    cudaFuncSetAttribute(fused_k, cudaFuncAttributeMaxDynamicSharedMemorySize, smem_bytes);

    fused_k<<<NPART, NTHREADS, smem_bytes>>>(gaussian, logp, pos, sigma, randind,
                                             out, wout, rout);
}

// round 7
// speedup vs baseline: 1.3458x; 1.3458x over previous
#include <cuda_runtime.h>
#include <cuda_bf16.h>
#include <cstddef>

#define NPART 128
#define NDIM  128
#define BATCH 4096
#define NTHREADS 256
#define TILE_B 64          // b staged per tile; warp handles 4 (+4 in group 2)

// ---------------------------------------------------------------------------
// Fused kernel: one CTA per particle, 256 threads, 8 warps.
// Microkernel: lane = 4 i (LDS.128), warp = 4 b (group1) + 4 b (group2).
// Per warp per j: 1 LDS.128 + 4 (or 8) broadcasts -> 16 (or 32) FFMA.
// ---------------------------------------------------------------------------
__global__ __launch_bounds__(NTHREADS) void fused_k(
    const float* __restrict__ gaussian,
    const float* __restrict__ logp,
    const float* __restrict__ pos,
    const float* __restrict__ sigma,
    const int*   __restrict__ randind,
    float*       __restrict__ out,
    float*       __restrict__ wout,
    float*       __restrict__ rout)
{
    extern __shared__ float smem[];
    float* sig_t = smem;                 // [128][128] transposed sigma (64KB)
    float* ysh   = smem + NDIM * NDIM;   // [TILE_B][128] (32KB)
    __shared__ int   list[BATCH];        // sample indices (16KB)
    __shared__ int   s_count;
    __shared__ float s_pp;

    const int p   = blockIdx.x;
    const int tid = threadIdx.x;
    const int w   = tid >> 5;
    const int l   = tid & 31;

    if (tid == 0) s_count = 0;
    __syncthreads();

    // ---- sigma staging setup: thread owns row si, 64-col half sh ----
    const int si = tid & 127;
    const int sh = (tid >> 7) * 64;
    const float4* srow =
        (const float4*)(sigma + ((size_t)p * NDIM + si) * NDIM + sh);

    // issue first 8 sigma LDGs (long latency, overlapped below)
    float4 sv[8];
    #pragma unroll
    for (int k = 0; k < 8; k++) sv[k] = __ldg(&srow[k]);

    // ---- softmax via warp 0 shuffles (overlaps LDG latency) ----
    if (tid < 32) {
        float v0 = logp[l],      v1 = logp[l + 32];
        float v2 = logp[l + 64], v3 = logp[l + 96];
        float m = fmaxf(fmaxf(v0, v1), fmaxf(v2, v3));
        #pragma unroll
        for (int s = 16; s > 0; s >>= 1)
            m = fmaxf(m, __shfl_xor_sync(0xffffffffu, m, s));
        float e = __expf(v0 - m) + __expf(v1 - m) + __expf(v2 - m) + __expf(v3 - m);
        #pragma unroll
        for (int s = 16; s > 0; s >>= 1)
            e += __shfl_xor_sync(0xffffffffu, e, s);
        if (l == 0) s_pp = __expf(logp[p] - m) / e;
    }

    // ---- scan randind, collect own samples (overlaps LDG latency) ----
    #pragma unroll
    for (int q = 0; q < BATCH / NTHREADS; q++) {
        int b = tid + q * NTHREADS;
        int r = __ldg(&randind[b]);
        if (r == p) {
            int slot = atomicAdd(&s_count, 1);
            list[slot] = b;
        }
    }

    // ---- second 8 sigma LDGs, then both STS passes (conflict-free) ----
    float4 sv2[8];
    #pragma unroll
    for (int k = 0; k < 8; k++) sv2[k] = __ldg(&srow[8 + k]);

    #pragma unroll
    for (int k = 0; k < 8; k++) {
        int j = sh + 4 * k;
        sig_t[(j + 0) * NDIM + si] = sv[k].x;
        sig_t[(j + 1) * NDIM + si] = sv[k].y;
        sig_t[(j + 2) * NDIM + si] = sv[k].z;
        sig_t[(j + 3) * NDIM + si] = sv[k].w;
    }
    #pragma unroll
    for (int k = 0; k < 8; k++) {
        int j = sh + 32 + 4 * k;
        sig_t[(j + 0) * NDIM + si] = sv2[k].x;
        sig_t[(j + 1) * NDIM + si] = sv2[k].y;
        sig_t[(j + 2) * NDIM + si] = sv2[k].z;
        sig_t[(j + 3) * NDIM + si] = sv2[k].w;
    }

    __syncthreads();                     // list, count, sig_t, s_pp ready
    const int count = s_count;
    const float pp  = s_pp;

    // ---- aux outputs ----
    for (int gi = tid; gi < count; gi += NTHREADS) {
        int b = list[gi];
        if (wout) wout[b] = pp;
        if (rout) rout[b] = (float)p;
    }

    const int i0 = 4 * l;
    const float4 pv = __ldg((const float4*)(pos + (size_t)p * NDIM + i0));

    const int ntiles = (count + TILE_B - 1) / TILE_B;   // 1 for ~all CTAs

    for (int t = 0; t < ntiles; t++) {
        const int tbase = t * TILE_B;
        const int rows  = min(count - tbase, TILE_B);

        if (t > 0) __syncthreads();
        // stage y rows [tbase, tbase+rows)
        for (int idx = tid; idx < rows * 32; idx += NTHREADS) {
            int r  = idx >> 5;
            int c4 = idx & 31;
            float4 v = __ldg((const float4*)(gaussian +
                              (size_t)list[tbase + r] * NDIM) + c4);
            *((float4*)(ysh + r * NDIM) + c4) = v;
        }
        __syncthreads();

        const int b1 = w * 4;            // group-1 base (within tile)
        const int b2 = 32 + w * 4;       // group-2 base
        const bool g1 = (b1 < rows);
        const bool g2 = (b2 < rows);

        float4 a0 = {0,0,0,0}, a1 = {0,0,0,0}, a2 = {0,0,0,0}, a3 = {0,0,0,0};
        float4 c0 = {0,0,0,0}, c1 = {0,0,0,0}, c2 = {0,0,0,0}, c3 = {0,0,0,0};

        const float* y10 = ysh + (b1 + 0) * NDIM;
        const float* y11 = ysh + (b1 + 1) * NDIM;
        const float* y12 = ysh + (b1 + 2) * NDIM;
        const float* y13 = ysh + (b1 + 3) * NDIM;
        const float* y20 = ysh + (b2 + 0) * NDIM;
        const float* y21 = ysh + (b2 + 1) * NDIM;
        const float* y22 = ysh + (b2 + 2) * NDIM;
        const float* y23 = ysh + (b2 + 3) * NDIM;

        if (g2) {
            #pragma unroll 8
            for (int j = 0; j < NDIM; j++) {
                float4 s = *(const float4*)(sig_t + j * NDIM + i0);
                float v0 = y10[j], v1 = y11[j], v2 = y12[j], v3 = y13[j];
                float u0 = y20[j], u1 = y21[j], u2 = y22[j], u3 = y23[j];
                a0.x = fmaf(s.x, v0, a0.x); a0.y = fmaf(s.y, v0, a0.y);
                a0.z = fmaf(s.z, v0, a0.z); a0.w = fmaf(s.w, v0, a0.w);
                a1.x = fmaf(s.x, v1, a1.x); a1.y = fmaf(s.y, v1, a1.y);
                a1.z = fmaf(s.z, v1, a1.z); a1.w = fmaf(s.w, v1, a1.w);
                a2.x = fmaf(s.x, v2, a2.x); a2.y = fmaf(s.y, v2, a2.y);
                a2.z = fmaf(s.z, v2, a2.z); a2.w = fmaf(s.w, v2, a2.w);
                a3.x = fmaf(s.x, v3, a3.x); a3.y = fmaf(s.y, v3, a3.y);
                a3.z = fmaf(s.z, v3, a3.z); a3.w = fmaf(s.w, v3, a3.w);
                c0.x = fmaf(s.x, u0, c0.x); c0.y = fmaf(s.y, u0, c0.y);
                c0.z = fmaf(s.z, u0, c0.z); c0.w = fmaf(s.w, u0, c0.w);
                c1.x = fmaf(s.x, u1, c1.x); c1.y = fmaf(s.y, u1, c1.y);
                c1.z = fmaf(s.z, u1, c1.z); c1.w = fmaf(s.w, u1, c1.w);
                c2.x = fmaf(s.x, u2, c2.x); c2.y = fmaf(s.y, u2, c2.y);
                c2.z = fmaf(s.z, u2, c2.z); c2.w = fmaf(s.w, u2, c2.w);
                c3.x = fmaf(s.x, u3, c3.x); c3.y = fmaf(s.y, u3, c3.y);
                c3.z = fmaf(s.z, u3, c3.z); c3.w = fmaf(s.w, u3, c3.w);
            }
        } else if (g1) {
            #pragma unroll 8
            for (int j = 0; j < NDIM; j++) {
                float4 s = *(const float4*)(sig_t + j * NDIM + i0);
                float v0 = y10[j], v1 = y11[j], v2 = y12[j], v3 = y13[j];
                a0.x = fmaf(s.x, v0, a0.x); a0.y = fmaf(s.y, v0, a0.y);
                a0.z = fmaf(s.z, v0, a0.z); a0.w = fmaf(s.w, v0, a0.w);
                a1.x = fmaf(s.x, v1, a1.x); a1.y = fmaf(s.y, v1, a1.y);
                a1.z = fmaf(s.z, v1, a1.z); a1.w = fmaf(s.w, v1, a1.w);
                a2.x = fmaf(s.x, v2, a2.x); a2.y = fmaf(s.y, v2, a2.y);
                a2.z = fmaf(s.z, v2, a2.z); a2.w = fmaf(s.w, v2, a2.w);
                a3.x = fmaf(s.x, v3, a3.x); a3.y = fmaf(s.y, v3, a3.y);
                a3.z = fmaf(s.z, v3, a3.z); a3.w = fmaf(s.w, v3, a3.w);
            }
        }

        // ---- epilogue ----
        if (g1) {
            float4 acc[4] = {a0, a1, a2, a3};
            #pragma unroll
            for (int bb = 0; bb < 3 + 1; bb++) {
                int gi = tbase + b1 + bb;
                if (gi < count) {
                    int b = list[gi];
                    float4 o;
                    o.x = pv.x + acc[bb].x; o.y = pv.y + acc[bb].y;
                    o.z = pv.z + acc[bb].z; o.w = pv.w + acc[bb].w;
                    *(float4*)(out + (size_t)b * NDIM + i0) = o;
                }
            }
        }
        if (g2) {
            float4 acc[4] = {c0, c1, c2, c3};
            #pragma unroll
            for (int bb = 0; bb < 4; bb++) {
                int gi = tbase + b2 + bb;
                if (gi < count) {
                    int b = list[gi];
                    float4 o;
                    o.x = pv.x + acc[bb].x; o.y = pv.y + acc[bb].y;
                    o.z = pv.z + acc[bb].z; o.w = pv.w + acc[bb].w;
                    *(float4*)(out + (size_t)b * NDIM + i0) = o;
                }
            }
        }
    }
}

// ---------------------------------------------------------------------------
// Launch
// ---------------------------------------------------------------------------
extern "C" void kernel_launch(void* const* d_in, const int* in_sizes, int n_in,
                              void* d_out, int out_size)
{
    const float* gaussian = nullptr;
    const float* logp     = nullptr;
    const float* pos      = nullptr;
    const float* sigma    = nullptr;
    const int*   randind  = nullptr;

    for (int k = 0; k < n_in; k++) {
        switch (in_sizes[k]) {
            case BATCH * NDIM:        gaussian = (const float*)d_in[k]; break;
            case NPART:               logp     = (const float*)d_in[k]; break;
            case NPART * NDIM:        pos      = (const float*)d_in[k]; break;
            case NPART * NDIM * NDIM: sigma    = (const float*)d_in[k]; break;
            case BATCH:               randind  = (const int*)d_in[k];   break;
            default: break;
        }
    }

    float* out  = (float*)d_out;
    float* wout = nullptr;
    float* rout = nullptr;
    const int OUT_MAIN = BATCH * NDIM;
    if (out_size >= OUT_MAIN + BATCH)     wout = out + OUT_MAIN;
    if (out_size >= OUT_MAIN + 2 * BATCH) rout = out + OUT_MAIN + BATCH;

    const int smem_bytes = (NDIM * NDIM + TILE_B * NDIM) * (int)sizeof(float); // 98304
    cudaFuncSetAttribute(fused_k, cudaFuncAttributeMaxDynamicSharedMemorySize, smem_bytes);

    fused_k<<<NPART, NTHREADS, smem_bytes>>>(gaussian, logp, pos, sigma, randind,
                                             out, wout, rout);
}